// round 2
// baseline (speedup 1.0000x reference)
#include <cuda_runtime.h>
#include <cstdint>

// Problem constants (fixed by setup_inputs)
#define EN 1000000       // total embedding rows
#define DN 128           // embedding dim
#define CN 262144        // cache rows
#define NN 16384         // number of ids
#define W_ALL 31250      // EN/32 bitmap words (EN divisible by 32)
#define W_C   8192       // CN/32
#define W_MISS (W_ALL - W_C)   // 23058 words covering rows [C, E)
#define T_CS 8192        // threads in counting-sort passes
#define K_CS 32          // slots per thread (T_CS*K_CS == CN)
#define NBUCK 100        // freq values are in [0, 100)

// -------- scratch (no allocations allowed) --------
__device__ int g_is64;
__device__ unsigned int g_present[W_ALL];          // bitmap: row appears in ids
__device__ unsigned int g_prot[W_C];               // bitmap: slot protected (hit)
__device__ int g_missScan[W_MISS];                 // exclusive popcount scan over words >= W_C
__device__ unsigned char g_histT[NBUCK * T_CS];    // per-thread bucket hist, transposed [v][t]
__device__ int g_threadBase[NBUCK * T_CS];         // exclusive scan across threads per bucket
__device__ int g_total[NBUCK];
__device__ int g_valueBase[NBUCK];
__device__ int g_slotAtRank[NN];                   // first NN entries of stable LFU order

// index-array load that tolerates int32-vs-int64 canonicalization
__device__ __forceinline__ long long ld_idx(const void* p, long long i) {
    if (g_is64) return ((const long long*)p)[i];
    return (long long)((const int*)p)[i];
}

// -------- K0: clear scratch + detect index width --------
__global__ void k_clear(const void* ids) {
    int i = blockIdx.x * blockDim.x + threadIdx.x;
    if (i < W_ALL) g_present[i] = 0u;
    if (i < W_C)   g_prot[i] = 0u;
    if (i == 0) {
        const long long* p = (const long long*)ids;
        int ok = 1;
        #pragma unroll
        for (int k = 0; k < 8; k++) {
            long long v = p[k];
            if (v < 0 || v >= (long long)EN) ok = 0;
        }
        g_is64 = ok;
    }
}

// -------- K1: scatter presence bits + protected-slot bits --------
__global__ void k_scatter(const void* ids, const void* idx_map, const void* inv) {
    int i = blockIdx.x * blockDim.x + threadIdx.x;
    if (i >= NN) return;
    long long id  = ld_idx(ids, i);
    long long row = ld_idx(idx_map, id);
    atomicOr(&g_present[row >> 5], 1u << (row & 31));
    long long slot = ld_idx(inv, row);
    if (slot >= 0) atomicOr(&g_prot[slot >> 5], 1u << (slot & 31));
}

// -------- K2: exclusive scan of popcounts over words [W_C, W_ALL) (single block) --------
__global__ void k_missScan() {
    __shared__ int ws[32];
    __shared__ int carrySh;
    int tid  = threadIdx.x;
    int lane = tid & 31, wid = tid >> 5;
    if (tid == 0) carrySh = 0;
    __syncthreads();
    for (int base = 0; base < W_MISS; base += 1024) {
        int w = base + tid;
        int v = (w < W_MISS) ? __popc(g_present[W_C + w]) : 0;
        int x = v;
        #pragma unroll
        for (int o = 1; o < 32; o <<= 1) {
            int y = __shfl_up_sync(0xffffffffu, x, o);
            if (lane >= o) x += y;
        }
        if (lane == 31) ws[wid] = x;
        __syncthreads();
        if (wid == 0) {
            int s = ws[lane];
            #pragma unroll
            for (int o = 1; o < 32; o <<= 1) {
                int y = __shfl_up_sync(0xffffffffu, s, o);
                if (lane >= o) s += y;
            }
            ws[lane] = s;
        }
        __syncthreads();
        int pre = (wid ? ws[wid - 1] : 0) + x - v;  // block-exclusive
        int carry = carrySh;
        if (w < W_MISS) g_missScan[w] = carry + pre;
        __syncthreads();
        if (tid == 0) carrySh = carry + ws[31];
        __syncthreads();
    }
}

// -------- K3: counting-sort pass 1 — per-thread bucket histograms --------
__global__ void k_hist(const void* cached, const void* freq) {
    int t = blockIdx.x * blockDim.x + threadIdx.x;  // [0, T_CS)
    unsigned char h[NBUCK];
    #pragma unroll
    for (int v = 0; v < NBUCK; v++) h[v] = 0;
    int s0 = t * K_CS;
    for (int j = 0; j < K_CS; j++) {
        int s = s0 + j;
        if ((g_prot[s >> 5] >> (s & 31)) & 1u) continue;  // protected -> sorts last, never used
        long long cr = ld_idx(cached, s);
        long long crc = cr < 0 ? 0 : (cr >= EN ? EN - 1 : cr);
        int v = (int)ld_idx(freq, crc);
        v = v < 0 ? 0 : (v > NBUCK - 1 ? NBUCK - 1 : v);
        h[v]++;
    }
    #pragma unroll
    for (int v = 0; v < NBUCK; v++) g_histT[v * T_CS + t] = h[v];
}

// -------- K4: per-bucket exclusive scan across threads (one block per bucket) --------
__global__ void k_scan_value() {
    int v = blockIdx.x;
    int tid = threadIdx.x;          // 1024 threads, 8 elements each
    int lane = tid & 31, wid = tid >> 5;
    __shared__ int ws[32];
    const unsigned char* hp = g_histT + v * T_CS;
    int base = tid * 8;
    uchar4 a = *(const uchar4*)(hp + base);
    uchar4 b = *(const uchar4*)(hp + base + 4);
    int e[8] = {a.x, a.y, a.z, a.w, b.x, b.y, b.z, b.w};
    int sum = e[0] + e[1] + e[2] + e[3] + e[4] + e[5] + e[6] + e[7];
    int x = sum;
    #pragma unroll
    for (int o = 1; o < 32; o <<= 1) {
        int y = __shfl_up_sync(0xffffffffu, x, o);
        if (lane >= o) x += y;
    }
    if (lane == 31) ws[wid] = x;
    __syncthreads();
    if (wid == 0) {
        int s = ws[lane];
        #pragma unroll
        for (int o = 1; o < 32; o <<= 1) {
            int y = __shfl_up_sync(0xffffffffu, s, o);
            if (lane >= o) s += y;
        }
        ws[lane] = s;
    }
    __syncthreads();
    int ex = (wid ? ws[wid - 1] : 0) + x - sum;
    int* tb = g_threadBase + v * T_CS + base;
    int run = ex;
    #pragma unroll
    for (int k = 0; k < 8; k++) { tb[k] = run; run += e[k]; }
    if (tid == 0) g_total[v] = ws[31];
}

// -------- K5: exclusive scan over bucket totals (tiny) --------
__global__ void k_valueBase() {
    if (threadIdx.x == 0) {
        int run = 0;
        for (int v = 0; v < NBUCK; v++) { g_valueBase[v] = run; run += g_total[v]; }
    }
}

// -------- K6: counting-sort placement — write first NN positions of stable order --------
__global__ void k_place(const void* cached, const void* freq) {
    int t = blockIdx.x * blockDim.x + threadIdx.x;
    unsigned char h[NBUCK];
    #pragma unroll
    for (int v = 0; v < NBUCK; v++) h[v] = 0;
    int s0 = t * K_CS;
    for (int j = 0; j < K_CS; j++) {
        int s = s0 + j;
        if ((g_prot[s >> 5] >> (s & 31)) & 1u) continue;
        long long cr = ld_idx(cached, s);
        long long crc = cr < 0 ? 0 : (cr >= EN ? EN - 1 : cr);
        int v = (int)ld_idx(freq, crc);
        v = v < 0 ? 0 : (v > NBUCK - 1 ? NBUCK - 1 : v);
        int pos = g_valueBase[v] + g_threadBase[v * T_CS + t] + (int)h[v];
        h[v]++;
        if (pos < NN) g_slotAtRank[pos] = s;
    }
}

// -------- K7: final gather — one warp per output row --------
// idxMode: 0 = no idx output, 1 = one float per idx, 2 = raw int64 (2 f32 slots)
__global__ void k_gather(const void* ids, const void* idx_map, const void* inv,
                         const float* __restrict__ weight, const float* __restrict__ cw,
                         float* outIdx, int idxMode, float* __restrict__ outVec) {
    int gt = blockIdx.x * blockDim.x + threadIdx.x;
    int i = gt >> 5;           // output row
    int lane = gt & 31;
    if (i >= NN) return;
    long long id   = ld_idx(ids, i);
    long long row  = ld_idx(idx_map, id);
    long long slot = ld_idx(inv, row);
    long long g;
    const float* src;
    if (slot >= 0) {                       // hit
        g = slot;
        src = cw + (size_t)g * DN;
    } else {                               // miss: rank among sorted unique missed rows
        int w = (int)(row >> 5);
        unsigned int below = g_present[w] & ((1u << (row & 31)) - 1u);
        int rank = g_missScan[w - W_C] + __popc(below);
        g = g_slotAtRank[rank];
        src = weight + (size_t)row * DN;   // weight_new[u] == weight[u] for u >= C
    }
    if (lane == 0) {
        if (idxMode == 1) outIdx[i] = (float)g;
        else if (idxMode == 2) ((long long*)outIdx)[i] = g;
    }
    float4* dst = (float4*)(outVec + (size_t)i * DN);
    dst[lane] = ((const float4*)src)[lane];
}

extern "C" void kernel_launch(void* const* d_in, const int* in_sizes, int n_in,
                              void* d_out, int out_size) {
    const void* ids     = d_in[0];
    const void* idx_map = d_in[1];
    const void* cached  = d_in[2];
    const void* inv     = d_in[3];
    const void* freq    = d_in[4];
    const float* weight = (const float*)d_in[5];
    const float* cw     = (const float*)d_in[6];

    k_clear   <<<(W_ALL + 255) / 256, 256>>>(ids);
    k_scatter <<<(NN + 255) / 256, 256>>>(ids, idx_map, inv);
    k_missScan<<<1, 1024>>>();
    k_hist    <<<T_CS / 256, 256>>>(cached, freq);
    k_scan_value<<<NBUCK, 1024>>>();
    k_valueBase<<<1, 32>>>();
    k_place   <<<T_CS / 256, 256>>>(cached, freq);

    // Output layout: tuple (gpu_row_idxs, out) flattened+concatenated.
    // Detect which variant the harness allocated from out_size.
    float* outIdx = nullptr;
    float* outVec = (float*)d_out;
    int idxMode = 0;
    long long total = (long long)out_size;
    if (total >= (long long)NN * DN + 2 * NN) {
        // idxs stored as raw int64 (2 x 4-byte elements each), then vectors
        outIdx = (float*)d_out;
        outVec = (float*)d_out + 2 * NN;
        idxMode = 2;
    } else if (total >= (long long)NN * DN + NN) {
        // idxs stored as one element each (cast to output dtype), then vectors
        outIdx = (float*)d_out;
        outVec = (float*)d_out + NN;
        idxMode = 1;
    }
    k_gather  <<<(NN * 32 + 255) / 256, 256>>>(ids, idx_map, inv, weight, cw,
                                               outIdx, idxMode, outVec);
}

// round 3
// speedup vs baseline: 2.0952x; 2.0952x over previous
#include <cuda_runtime.h>
#include <cstdint>

// Problem constants (fixed by setup_inputs)
#define EN 1000000       // total embedding rows
#define DN 128           // embedding dim
#define CN 262144        // cache rows
#define NN 16384         // number of ids
#define W_ALL 31250      // EN/32 bitmap words
#define W_C   8192       // CN/32
#define W_MISS (W_ALL - W_C)   // 23058 words covering rows [C, E)
#define NB 101           // buckets: key -1 -> 0, freq v -> v+1 (freq in [0,100))
#define WARPS_TOT 1024   // warps in counting-sort passes
#define SPW 256          // slots per warp (WARPS_TOT*SPW == CN)
#define MS_CH 23         // missScan items per thread (1024*23 >= W_MISS)
#define MS_PAD (1024*MS_CH)

// -------- scratch (no allocations allowed) --------
__device__ int g_is64;
__device__ unsigned int g_present[W_ALL];
__device__ unsigned int g_prot[W_C];
__device__ int g_missScan[W_MISS];
__device__ int g_histW[NB * WARPS_TOT];     // per-warp bucket counts, [bucket][warp]
__device__ int g_warpBase[NB * WARPS_TOT];  // exclusive scan across warps per bucket
__device__ int g_total[NB];
__device__ int g_slotAtRank[NN];

__device__ __forceinline__ long long ld_idx(const void* p, long long i) {
    if (g_is64) return ((const long long*)p)[i];
    return (long long)((const int*)p)[i];
}

// -------- K0: clear bitmaps + detect index width --------
__global__ void k_clear(const void* ids) {
    int i = blockIdx.x * blockDim.x + threadIdx.x;
    if (i < W_ALL) g_present[i] = 0u;
    if (i < W_C)   g_prot[i] = 0u;
    if (i == 0) {
        const long long* p = (const long long*)ids;
        int ok = 1;
        #pragma unroll
        for (int k = 0; k < 8; k++) {
            long long v = p[k];
            if (v < 0 || v >= (long long)EN) ok = 0;
        }
        g_is64 = ok;
    }
}

// -------- K1: scatter presence + protected-slot bits --------
__global__ void k_scatter(const void* ids, const void* idx_map, const void* inv) {
    int i = blockIdx.x * blockDim.x + threadIdx.x;
    if (i >= NN) return;
    long long id  = ld_idx(ids, i);
    long long row = ld_idx(idx_map, id);
    atomicOr(&g_present[row >> 5], 1u << (row & 31));
    long long slot = ld_idx(inv, row);
    if (slot >= 0) atomicOr(&g_prot[slot >> 5], 1u << (slot & 31));
}

// -------- K2: popcount exclusive scan over words [W_C, W_ALL), one block --------
__global__ void k_missScan() {
    __shared__ unsigned char pc[MS_PAD];
    __shared__ int ws[32];
    int tid = threadIdx.x, lane = tid & 31, wid = tid >> 5;
    for (int i = tid; i < MS_PAD; i += 1024)
        pc[i] = (i < W_MISS) ? (unsigned char)__popc(g_present[W_C + i]) : 0;
    __syncthreads();
    int base = tid * MS_CH;
    int sum = 0;
    #pragma unroll
    for (int k = 0; k < MS_CH; k++) sum += pc[base + k];
    // block exclusive scan of per-thread sums
    int x = sum;
    #pragma unroll
    for (int o = 1; o < 32; o <<= 1) {
        int y = __shfl_up_sync(0xffffffffu, x, o);
        if (lane >= o) x += y;
    }
    if (lane == 31) ws[wid] = x;
    __syncthreads();
    if (wid == 0) {
        int s = ws[lane];
        #pragma unroll
        for (int o = 1; o < 32; o <<= 1) {
            int y = __shfl_up_sync(0xffffffffu, s, o);
            if (lane >= o) s += y;
        }
        ws[lane] = s;
    }
    __syncthreads();
    int run = (wid ? ws[wid - 1] : 0) + x - sum;
    #pragma unroll
    for (int k = 0; k < MS_CH; k++) {
        int w = base + k;
        if (w < W_MISS) g_missScan[w] = run;
        run += pc[base + k];
    }
}

// shared helper: compute bucket keys + protected mask words for one warp's 256 slots
struct WarpKeys { int v[8]; unsigned int protw; };
__device__ __forceinline__ WarpKeys load_keys(const void* cached, const void* freq,
                                              int s0, int lane) {
    WarpKeys r;
    r.protw = (lane < 8) ? g_prot[(s0 >> 5) + lane] : 0u;
    long long cr[8];
    #pragma unroll
    for (int j = 0; j < 8; j++) cr[j] = ld_idx(cached, s0 + j * 32 + lane);
    #pragma unroll
    for (int j = 0; j < 8; j++) {
        long long c = cr[j];
        if (c < 0) r.v[j] = 0;                     // key -1 -> bucket 0
        else {
            long long cc = c >= EN ? EN - 1 : c;
            int f = (int)ld_idx(freq, cc);
            f = f < 0 ? 0 : (f > 99 ? 99 : f);
            r.v[j] = f + 1;
        }
    }
    return r;
}

// -------- K3: per-warp bucket histograms (stable counting sort, pass 1) --------
__global__ void k_hist(const void* cached, const void* freq) {
    __shared__ int sh[8][NB];
    int lane = threadIdx.x & 31, wid = threadIdx.x >> 5;
    int wg = blockIdx.x * 8 + wid;
    for (int i = lane; i < NB; i += 32) sh[wid][i] = 0;
    __syncwarp();
    int s0 = wg * SPW;
    WarpKeys K = load_keys(cached, freq, s0, lane);
    #pragma unroll
    for (int j = 0; j < 8; j++) {
        unsigned int pw = __shfl_sync(0xffffffffu, K.protw, j);
        int key = ((pw >> lane) & 1u) ? NB : K.v[j];   // protected -> dropped
        unsigned int mask = __match_any_sync(0xffffffffu, key);
        if (lane == (__ffs(mask) - 1) && key < NB) sh[wid][key] += __popc(mask);
        __syncwarp();
    }
    for (int i = lane; i < NB; i += 32) g_histW[i * WARPS_TOT + wg] = sh[wid][i];
}

// -------- K4: per-bucket exclusive scan across the 1024 warps --------
__global__ void k_scan() {
    __shared__ int ws[32];
    int v = blockIdx.x, t = threadIdx.x, lane = t & 31, wid = t >> 5;
    int val = g_histW[v * WARPS_TOT + t];
    int x = val;
    #pragma unroll
    for (int o = 1; o < 32; o <<= 1) {
        int y = __shfl_up_sync(0xffffffffu, x, o);
        if (lane >= o) x += y;
    }
    if (lane == 31) ws[wid] = x;
    __syncthreads();
    if (wid == 0) {
        int s = ws[lane];
        #pragma unroll
        for (int o = 1; o < 32; o <<= 1) {
            int y = __shfl_up_sync(0xffffffffu, s, o);
            if (lane >= o) s += y;
        }
        ws[lane] = s;
    }
    __syncthreads();
    int ex = (wid ? ws[wid - 1] : 0) + x - val;
    g_warpBase[v * WARPS_TOT + t] = ex;
    if (t == WARPS_TOT - 1) g_total[v] = ex + val;
}

// -------- K5: placement — write first NN positions of the stable LFU order --------
__global__ void k_place(const void* cached, const void* freq) {
    __shared__ int cur[8][NB];
    __shared__ int vb[NB];
    int lane = threadIdx.x & 31, wid = threadIdx.x >> 5;
    int wg = blockIdx.x * 8 + wid;
    // bucket-total exclusive scan (warp 0, 4 chunks of 32)
    if (wid == 0) {
        int run = 0;
        #pragma unroll
        for (int b = 0; b < NB; b += 32) {
            int idx = b + lane;
            int tv = (idx < NB) ? g_total[idx] : 0;
            int x = tv;
            #pragma unroll
            for (int o = 1; o < 32; o <<= 1) {
                int y = __shfl_up_sync(0xffffffffu, x, o);
                if (lane >= o) x += y;
            }
            if (idx < NB) vb[idx] = run + x - tv;
            run += __shfl_sync(0xffffffffu, x, 31);
        }
    }
    __syncthreads();
    for (int i = lane; i < NB; i += 32)
        cur[wid][i] = vb[i] + g_warpBase[i * WARPS_TOT + wg];
    __syncwarp();
    int s0 = wg * SPW;
    WarpKeys K = load_keys(cached, freq, s0, lane);
    unsigned int lmask_lt = (1u << lane) - 1u;
    #pragma unroll
    for (int j = 0; j < 8; j++) {
        unsigned int pw = __shfl_sync(0xffffffffu, K.protw, j);
        int key = ((pw >> lane) & 1u) ? NB : K.v[j];
        unsigned int mask = __match_any_sync(0xffffffffu, key);
        int prefix = __popc(mask & lmask_lt);
        int leader = __ffs(mask) - 1;
        int base = 0;
        if (lane == leader && key < NB) {
            base = cur[wid][key];
            cur[wid][key] = base + __popc(mask);
        }
        base = __shfl_sync(0xffffffffu, base, leader);
        int pos = base + prefix;
        if (key < NB && pos < NN) g_slotAtRank[pos] = s0 + j * 32 + lane;
        __syncwarp();
    }
}

// -------- K6: final gather — one warp per output row --------
// idxMode: 0 = no idx output, 1 = one float per idx, 2 = raw int64 (2 f32 slots)
__global__ void k_gather(const void* ids, const void* idx_map, const void* inv,
                         const float* __restrict__ weight, const float* __restrict__ cw,
                         float* outIdx, int idxMode, float* __restrict__ outVec) {
    int gt = blockIdx.x * blockDim.x + threadIdx.x;
    int i = gt >> 5;
    int lane = gt & 31;
    if (i >= NN) return;
    long long id   = ld_idx(ids, i);
    long long row  = ld_idx(idx_map, id);
    long long slot = ld_idx(inv, row);
    long long g;
    const float* src;
    if (slot >= 0) {
        g = slot;
        src = cw + (size_t)g * DN;
    } else {
        int w = (int)(row >> 5);
        unsigned int below = g_present[w] & ((1u << (row & 31)) - 1u);
        int rank = g_missScan[w - W_C] + __popc(below);
        g = g_slotAtRank[rank];
        src = weight + (size_t)row * DN;   // write-back never touches rows >= C
    }
    if (lane == 0) {
        if (idxMode == 1) outIdx[i] = (float)g;
        else if (idxMode == 2) ((long long*)outIdx)[i] = g;
    }
    float4* dst = (float4*)(outVec + (size_t)i * DN);
    dst[lane] = ((const float4*)src)[lane];
}

extern "C" void kernel_launch(void* const* d_in, const int* in_sizes, int n_in,
                              void* d_out, int out_size) {
    const void* ids     = d_in[0];
    const void* idx_map = d_in[1];
    const void* cached  = d_in[2];
    const void* inv     = d_in[3];
    const void* freq    = d_in[4];
    const float* weight = (const float*)d_in[5];
    const float* cw     = (const float*)d_in[6];

    k_clear   <<<(W_ALL + 255) / 256, 256>>>(ids);
    k_scatter <<<(NN + 255) / 256, 256>>>(ids, idx_map, inv);
    k_missScan<<<1, 1024>>>();
    k_hist    <<<WARPS_TOT / 8, 256>>>(cached, freq);
    k_scan    <<<NB, WARPS_TOT>>>();
    k_place   <<<WARPS_TOT / 8, 256>>>(cached, freq);

    float* outIdx = nullptr;
    float* outVec = (float*)d_out;
    int idxMode = 0;
    long long total = (long long)out_size;
    if (total >= (long long)NN * DN + 2 * NN) {
        outIdx = (float*)d_out;
        outVec = (float*)d_out + 2 * NN;
        idxMode = 2;
    } else if (total >= (long long)NN * DN + NN) {
        outIdx = (float*)d_out;
        outVec = (float*)d_out + NN;
        idxMode = 1;
    }
    k_gather  <<<(NN * 32 + 255) / 256, 256>>>(ids, idx_map, inv, weight, cw,
                                               outIdx, idxMode, outVec);
}